// round 16
// baseline (speedup 1.0000x reference)
#include <cuda_runtime.h>
#include <cuda_bf16.h>
#include <cstdint>

// ---------------------------------------------------------------------------
// Spikformer spatial+temporal SSA — bf16 mma.sync, cp.async double-buffered,
// register-cached b0 fragment, work-queue persistent GEMMs, bf16 spike
// storage (binary -> exact). R14 + unioned/bf16 phase2 smem + init fold.
// ---------------------------------------------------------------------------

#define TT 10
#define BB 4
#define CC 384
#define NN 384
#define HH 12
#define CN (CC * NN)             // 147456
#define TBCN (TT * BB * CC * NN) // 5898240
#define BCN (BB * CC * NN)       // 589824

// scratch (spike tensors in bf16 — binary values, exact)
__device__ __align__(128) __nv_bfloat16 g_q[TBCN];   // spatial q spikes [tb][c][n]
__device__ __align__(128) __nv_bfloat16 g_k[TBCN];
__device__ __align__(128) __nv_bfloat16 g_v[TBCN];
__device__ __align__(128) __nv_bfloat16 g_pq[TBCN];  // temporal proj spikes [tb][c][n]
__device__ __align__(128) __nv_bfloat16 g_pk[TBCN];
__device__ __align__(128) __nv_bfloat16 g_pv[TBCN];
__device__ __align__(128) __nv_bfloat16 g_a[TBCN];   // temporal final spikes
__device__ __align__(128) __nv_bfloat16 g_tq[TBCN];  // gathered [(n*B+b)*H+h][t*32+e]
__device__ __align__(128) __nv_bfloat16 g_tk[TBCN];
__device__ __align__(128) __nv_bfloat16 g_tv[TBCN];
__device__ __align__(128) float g_M[480 * 1024];                // spatial k^T v
__device__ __align__(128) __nv_bfloat16 g_osT[TBCN];            // spatial attn spikes [tb][n][c]
__device__ __align__(128) __nv_bfloat16 g_osT2[TBCN];           // temporal attn spikes [tb][n][c]
__device__ __align__(128) __nv_bfloat16 g_Wc[8 * 3 * CN];       // [mat][comp][o][c]
__device__ __align__(128) __nv_bfloat16 g_XT[2 * 3 * 40 * CN];  // [sel][comp][tb][n][c]
__device__ float g_ared[TT * BB * CC]; // raw row sums (spatial)
__device__ unsigned g_ctr_qkv;
__device__ unsigned g_ctr_fin;

__device__ __forceinline__ uint32_t smem_u32(const void* p) {
    uint32_t a;
    asm("{ .reg .u64 t; cvta.to.shared.u64 t, %1; cvt.u32.u64 %0, t; }"
        : "=r"(a) : "l"(p));
    return a;
}

__device__ __forceinline__ void ldsm_x4(uint32_t addr, uint32_t& r0, uint32_t& r1,
                                        uint32_t& r2, uint32_t& r3) {
    asm volatile("ldmatrix.sync.aligned.m8n8.x4.shared.b16 {%0,%1,%2,%3}, [%4];"
                 : "=r"(r0), "=r"(r1), "=r"(r2), "=r"(r3) : "r"(addr));
}

__device__ __forceinline__ void mma_bf16(float* c, const uint32_t* a,
                                         uint32_t b0, uint32_t b1) {
    asm volatile(
        "mma.sync.aligned.m16n8k16.row.col.f32.bf16.bf16.f32 "
        "{%0,%1,%2,%3}, {%4,%5,%6,%7}, {%8,%9}, {%0,%1,%2,%3};"
        : "+f"(c[0]), "+f"(c[1]), "+f"(c[2]), "+f"(c[3])
        : "r"(a[0]), "r"(a[1]), "r"(a[2]), "r"(a[3]), "r"(b0), "r"(b1));
}

__device__ __forceinline__ uint32_t swz64(uint32_t off) {
    return off ^ ((off >> 3) & 0x30);
}

__device__ __forceinline__ void cp16(uint32_t dst, const void* src) {
    asm volatile("cp.async.cg.shared.global [%0], [%1], 16;" :: "r"(dst), "l"(src));
}

#define SMEM_QKV 99328
#define SMEM_FIN 66560
// phase2 dynamic smem: temporal branch = 3*8*321*2 (bf16 panels) + 8*112*4 (at)
#define SMEM_P2 19008

// ---------------------------------------------------------------------------
// fp32 -> 3x bf16 exact split precompute (+ init folded into split_w tail)
// ---------------------------------------------------------------------------
__device__ __forceinline__ void split3(float x, __nv_bfloat16& a, __nv_bfloat16& b,
                                       __nv_bfloat16& c) {
    a = __float2bfloat16(x);
    float r = x - __bfloat162float(a);
    b = __float2bfloat16(r);
    float r2 = r - __bfloat162float(b);
    c = __float2bfloat16(r2);
}

// blocks [0,4608): W split; [4608,4668): init ared + counters
__global__ void __launch_bounds__(256) k_split_w(const float* __restrict__ sW,
                                                 const float* __restrict__ tW) {
    const int bx = blockIdx.x;
    if (bx >= 4608) {
        int i = (bx - 4608) * 256 + threadIdx.x;
        if (i < TT * BB * CC) g_ared[i] = 0.0f;
        if (i == 0) { g_ctr_qkv = 0u; g_ctr_fin = 0u; }
        return;
    }
    int i = bx * 256 + threadIdx.x;
    float w = (i < 4 * CN) ? sW[i] : tW[i - 4 * CN];
    int m = i / CN, e = i - m * CN;
    __nv_bfloat16 c1, c2, c3;
    split3(w, c1, c2, c3);
    size_t base = (size_t)m * 3 * CN + e;
    g_Wc[base] = c1;
    g_Wc[base + CN] = c2;
    g_Wc[base + 2 * CN] = c3;
}

__global__ void __launch_bounds__(256) k_split_xy(const float* __restrict__ x,
                                                  const float* __restrict__ y) {
    __shared__ float t[32][33];
    int bx = blockIdx.x;
    int sel = bx / 5760;
    int r = bx - sel * 5760;
    int tb = r / 144, tl = r - tb * 144;
    int ct = tl / 12, nt = tl - ct * 12;
    const float* src = (sel ? y : x) + (size_t)tb * CN + (size_t)(ct * 32) * NN + nt * 32;
    int tid = threadIdx.x;
#pragma unroll
    for (int i = 0; i < 4; ++i) {
        int idx = tid + i * 256;
        int cl = idx >> 5, nl = idx & 31;
        t[cl][nl] = src[(size_t)cl * NN + nl];
    }
    __syncthreads();
#pragma unroll
    for (int i = 0; i < 4; ++i) {
        int idx = tid + i * 256;
        int nl = idx >> 5, cl = idx & 31;
        __nv_bfloat16 c1, c2, c3;
        split3(t[cl][nl], c1, c2, c3);
        size_t base = ((size_t)(sel * 3) * 40 + tb) * CN + (size_t)(nt * 32 + nl) * CC + ct * 32 + cl;
        g_XT[base] = c1;
        g_XT[base + (size_t)40 * CN] = c2;
        g_XT[base + (size_t)80 * CN] = c3;
    }
}

// ---------------------------------------------------------------------------
// cp.async double-buffered tensor-core GEMM tile, register-cached b0 fragment,
// single __syncthreads per stage. Outputs bf16 spikes (or fused row-sum).
// ---------------------------------------------------------------------------
template <int NBC>
__device__ __forceinline__ void tc_gemm_body(
    const __nv_bfloat16* __restrict__ A0,
    const __nv_bfloat16* __restrict__ B0, size_t bcs,
    const float* __restrict__ gs, const float* __restrict__ bs,
    float* __restrict__ obf, __nv_bfloat16* __restrict__ obh,
    int o0, int n0, bool suma)
{
    constexpr int NC = 3 + NBC;
    constexpr uint32_t STAGE = NC * 8192u;
    extern __shared__ char smem_raw[];
    const uint32_t ab = (smem_u32(smem_raw) + 1023u) & ~1023u;
    const int tid = threadIdx.x;
    const int lane = tid & 31;
    const int wid = tid >> 5;
    const int wm = (wid >> 2) * 64;
    const int wn = (wid & 3) * 32;

    float acc[4][4][4];
#pragma unroll
    for (int mi = 0; mi < 4; ++mi)
#pragma unroll
        for (int ni = 0; ni < 4; ++ni)
#pragma unroll
            for (int r = 0; r < 4; ++r) acc[mi][ni][r] = 0.0f;

    const int a_row_l = lane & 15;
    const int a_ch = (lane >> 4) << 4;
    const int b_row_l = ((lane >> 4) & 1) * 8 + (lane & 7);
    const int b_ch = ((lane >> 3) & 1) << 4;

    auto load_stage = [&](int s, uint32_t buf) {
#pragma unroll
        for (int i = 0; i < NC * 2; ++i) {
            int idx = tid + i * 256;
            int comp = idx >> 9;
            int rem = idx & 511;
            int row = rem >> 2, ch = rem & 3;
            const __nv_bfloat16* g =
                (comp < 3) ? (A0 + (size_t)comp * CN) : (B0 + (size_t)(comp - 3) * bcs);
            g += (size_t)row * CC + s * 32 + ch * 8;
            uint32_t d = buf + comp * 8192 + swz64((uint32_t)(row * 64 + ch * 16));
            cp16(d, g);
        }
        asm volatile("cp.async.commit_group;" ::: "memory");
    };

    auto load_bf = [&](uint32_t base, int ks, uint32_t bf[4][2]) {
#pragma unroll
        for (int bi = 0; bi < 2; ++bi) {
            int row = wn + bi * 16 + b_row_l;
            uint32_t off = (uint32_t)(row * 64 + ks * 32 + b_ch);
            uint32_t r0, r1, r2, r3;
            ldsm_x4(base + swz64(off), r0, r1, r2, r3);
            bf[bi * 2][0] = r0; bf[bi * 2][1] = r1;
            bf[bi * 2 + 1][0] = r2; bf[bi * 2 + 1][1] = r3;
        }
    };
    auto load_af = [&](uint32_t base, int ks, int mi, uint32_t* af) {
        int row = wm + mi * 16 + a_row_l;
        uint32_t off = (uint32_t)(row * 64 + ks * 32 + a_ch);
        ldsm_x4(base + swz64(off), af[0], af[1], af[2], af[3]);
    };

    load_stage(0, ab);
    for (int s = 0; s < 12; ++s) {
        const uint32_t cur = ab + (uint32_t)(s & 1) * STAGE;
        asm volatile("cp.async.wait_group 0;" ::: "memory");
        __syncthreads();
        if (s < 11) load_stage(s + 1, ab + (uint32_t)((s + 1) & 1) * STAGE);

#pragma unroll
        for (int ks = 0; ks < 2; ++ks) {
            uint32_t b0[4][2];
            load_bf(cur + 3 * 8192, ks, b0); // pb=0, cached (used by all pa)
#pragma unroll
            for (int pa = 0; pa < 3; ++pa) {
                uint32_t afr[4][4];
#pragma unroll
                for (int mi = 0; mi < 4; ++mi) load_af(cur + pa * 8192, ks, mi, afr[mi]);
#pragma unroll
                for (int mi = 0; mi < 4; ++mi)
#pragma unroll
                    for (int ni = 0; ni < 4; ++ni)
                        mma_bf16(acc[mi][ni], afr[mi], b0[ni][0], b0[ni][1]);
                if (NBC == 3) {
                    if (pa < 2) { // pb=1 (pairs (0,1),(1,1))
                        uint32_t bt[4][2];
                        load_bf(cur + 4 * 8192, ks, bt);
#pragma unroll
                        for (int mi = 0; mi < 4; ++mi)
#pragma unroll
                            for (int ni = 0; ni < 4; ++ni)
                                mma_bf16(acc[mi][ni], afr[mi], bt[ni][0], bt[ni][1]);
                    }
                    if (pa == 0) { // pb=2 (pair (0,2))
                        uint32_t bt[4][2];
                        load_bf(cur + 5 * 8192, ks, bt);
#pragma unroll
                        for (int mi = 0; mi < 4; ++mi)
#pragma unroll
                            for (int ni = 0; ni < 4; ++ni)
                                mma_bf16(acc[mi][ni], afr[mi], bt[ni][0], bt[ni][1]);
                    }
                }
            }
        }
    }

    // epilogue: BN + spike. row = channel index (always in [0,384)).
#pragma unroll
    for (int mi = 0; mi < 4; ++mi) {
#pragma unroll
        for (int half = 0; half < 2; ++half) {
            const int row = o0 + wm + mi * 16 + half * 8 + (lane >> 2);
            const float gv = gs[row];
            const float bv = bs[row];
            float vals[8];
#pragma unroll
            for (int ni = 0; ni < 4; ++ni) {
                vals[ni * 2 + 0] = (fmaf(acc[mi][ni][half * 2 + 0], gv, bv) >= 2.0f) ? 1.f : 0.f;
                vals[ni * 2 + 1] = (fmaf(acc[mi][ni][half * 2 + 1], gv, bv) >= 2.0f) ? 1.f : 0.f;
            }
            if (suma) {
                float sum = 0.f;
#pragma unroll
                for (int j = 0; j < 8; ++j) sum += vals[j];
                sum += __shfl_xor_sync(0xffffffffu, sum, 1);
                sum += __shfl_xor_sync(0xffffffffu, sum, 2);
                if ((lane & 3) == 0) atomicAdd(&obf[row], sum);
            } else {
                __nv_bfloat16* dst = obh + (size_t)row * NN + n0 + wn + (lane & 3) * 2;
#pragma unroll
                for (int ni = 0; ni < 4; ++ni) {
                    __nv_bfloat162 w;
                    w.x = __float2bfloat16(vals[ni * 2 + 0]);
                    w.y = __float2bfloat16(vals[ni * 2 + 1]);
                    *(__nv_bfloat162*)(dst + ni * 8) = w;
                }
            }
        }
    }
}

// Work-queue persistent qkv for BOTH paths: 2160 tiles.
__global__ void __launch_bounds__(256, 2) k_qkv_all(
    const float* __restrict__ sg, const float* __restrict__ sb,
    const float* __restrict__ tg, const float* __restrict__ tb_)
{
    __shared__ unsigned s_tile;
    for (;;) {
        if (threadIdx.x == 0) s_tile = atomicAdd(&g_ctr_qkv, 1u);
        __syncthreads();
        unsigned tile = s_tile;
        if (tile >= 2160u) break;
        int nx = tile % 3;
        int rest = tile / 3;
        int my = rest % 3;
        int z = rest / 3;
        int pj = z / 40, tb = z - pj * 40;
        int path = pj / 3, j = pj - path * 3;
        int o0 = my * 128, n0 = nx * 128;
        const __nv_bfloat16* A0 = g_Wc + (size_t)((path * 4 + j) * 3) * CN + (size_t)o0 * CC;
        int sel = (j == 0) ? 0 : 1;
        const __nv_bfloat16* B0 = g_XT + ((size_t)(sel * 3) * 40 + tb) * CN + (size_t)n0 * CC;
        __nv_bfloat16* Ob;
        if (path == 0) Ob = (j == 0) ? g_q : (j == 1) ? g_k : g_v;
        else           Ob = (j == 0) ? g_pq : (j == 1) ? g_pk : g_pv;
        const float* gs = (path == 0) ? sg : tg;
        const float* bs = (path == 0) ? sb : tb_;
        tc_gemm_body<3>(A0, B0, (size_t)40 * CN, gs + j * CC, bs + j * CC,
                        nullptr, Ob + (size_t)tb * CN, o0, n0, false);
        __syncthreads();
    }
}

// Work-queue persistent merged final convs: 720 tiles.
__global__ void __launch_bounds__(256, 2) k_final_all(
    const float* __restrict__ sg, const float* __restrict__ sb,
    const float* __restrict__ tg, const float* __restrict__ tb_)
{
    __shared__ unsigned s_tile;
    for (;;) {
        if (threadIdx.x == 0) s_tile = atomicAdd(&g_ctr_fin, 1u);
        __syncthreads();
        unsigned tile = s_tile;
        if (tile >= 720u) break;
        int nx = tile % 3;
        int rest = tile / 3;
        int my = rest % 3;
        int z = rest / 3;
        int path = z / 40, tb = z - path * 40;
        int o0 = my * 128, n0 = nx * 128;
        const __nv_bfloat16* A0 = g_Wc + (size_t)((path * 4 + 3) * 3) * CN + (size_t)o0 * CC;
        const __nv_bfloat16* B0 =
            ((path == 0) ? g_osT : g_osT2) + (size_t)tb * CN + (size_t)n0 * CC;
        const float* gs = (path == 0) ? sg : tg;
        const float* bs = (path == 0) ? sb : tb_;
        tc_gemm_body<1>(A0, B0, 0, gs + 3 * CC, bs + 3 * CC,
                        g_ared + (size_t)tb * CC, g_a + (size_t)tb * CN,
                        o0, n0, path == 0);
        __syncthreads();
    }
}

// ---------------------------------------------------------------------------
// Phase 1 (merged): spatial kvM (blocks 0..479) + temporal gather (480..17759)
// ---------------------------------------------------------------------------
__global__ void __launch_bounds__(256) k_phase1() {
    const int bx = blockIdx.x;
    const int tid = threadIdx.x;
    if (bx < 480) {
        __shared__ float ks[64][33];
        __shared__ float vs[64][33];
        const int tb = bx / HH;
        const int h = bx - tb * HH;
        const size_t base = (size_t)tb * CN + (size_t)h * 32 * NN;
        const __nv_bfloat16* kb = g_k + base;
        const __nv_bfloat16* vb = g_v + base;

        const int e = tid >> 3;
        const int dd0 = (tid & 7) << 2;
        float mc0 = 0.f, mc1 = 0.f, mc2 = 0.f, mc3 = 0.f;
        for (int m0 = 0; m0 < NN; m0 += 64) {
#pragma unroll
            for (int i = 0; i < 8; ++i) {
                int idx = tid + i * 256;
                int ee = idx >> 6, mm = idx & 63;
                ks[mm][ee] = __bfloat162float(kb[(size_t)ee * NN + m0 + mm]);
                vs[mm][ee] = __bfloat162float(vb[(size_t)ee * NN + m0 + mm]);
            }
            __syncthreads();
#pragma unroll 8
            for (int mm = 0; mm < 64; ++mm) {
                float kv = ks[mm][e];
                mc0 = fmaf(kv, vs[mm][dd0 + 0], mc0);
                mc1 = fmaf(kv, vs[mm][dd0 + 1], mc1);
                mc2 = fmaf(kv, vs[mm][dd0 + 2], mc2);
                mc3 = fmaf(kv, vs[mm][dd0 + 3], mc3);
            }
            __syncthreads();
        }
        float* Mp = g_M + (size_t)bx * 1024 + e * 32 + dd0;
        Mp[0] = mc0; Mp[1] = mc1; Mp[2] = mc2; Mp[3] = mc3;
    } else {
        // temporal gather: dst[((n*B+b)*H+h)*320 + t*32 + e]
        __shared__ __nv_bfloat16 tile[32][33];
        const int r0 = bx - 480;
        const int which = r0 / 5760;
        const int r = r0 - which * 5760;
        const int ntile = r % 12;
        const int tbh = r / 12;
        const int tb = tbh / 12;
        const int h = tbh - tb * 12;
        const int t = tb / BB;
        const int b = tb - t * BB;

        const __nv_bfloat16* srcbase = (which == 0) ? g_pq : (which == 1) ? g_pk : g_pv;
        __nv_bfloat16* dst = (which == 0) ? g_tq : (which == 1) ? g_tk : g_tv;
        const __nv_bfloat16* src = srcbase + (size_t)tb * CN + (size_t)h * 32 * NN + ntile * 32;

#pragma unroll
        for (int i = 0; i < 4; ++i) {
            int idx = tid + i * 256;
            int ee = idx >> 5, nn = idx & 31;
            tile[ee][nn] = src[(size_t)ee * NN + nn];
        }
        __syncthreads();
#pragma unroll
        for (int i = 0; i < 4; ++i) {
            int idx = tid + i * 256;
            int nn = idx >> 5, ee = idx & 31;
            int n = ntile * 32 + nn;
            dst[((size_t)(n * BB + b) * HH + h) * 320 + t * 32 + ee] = tile[ee][nn];
        }
    }
}

// ---------------------------------------------------------------------------
// Phase 2 (merged, dynamic smem union): spatial qM (blocks 0..1439, 2 n/thread)
// + temporal attn (1440..3743, bf16 smem panels)
// ---------------------------------------------------------------------------
__global__ void __launch_bounds__(256) k_phase2() {
    extern __shared__ char dyn2[];
    const int bx = blockIdx.x;
    const int tid = threadIdx.x;
    if (bx < 1440) {
        float (*Ms)[32] = (float(*)[32])dyn2;
        const int tbh = bx / 3;
        const int nt = bx - tbh * 3;
        const int tb = tbh / HH;
        const int h = tbh - tb * HH;

#pragma unroll
        for (int i = 0; i < 4; ++i) {
            int idx = tid + i * 256;
            Ms[idx >> 5][idx & 31] = g_M[(size_t)tbh * 1024 + idx];
        }
        __syncthreads();

        const int np = tid & 63;
        const int n = nt * 128 + np * 2;
        const int d0 = (tid >> 6) * 8;
        const __nv_bfloat16* qb = g_q + (size_t)tb * CN + (size_t)h * 32 * NN + n;

        float acc0[8], acc1[8];
#pragma unroll
        for (int j = 0; j < 8; ++j) { acc0[j] = 0.f; acc1[j] = 0.f; }
#pragma unroll
        for (int e = 0; e < 32; ++e) {
            __nv_bfloat162 qp = *(const __nv_bfloat162*)(qb + (size_t)e * NN);
            float qv0 = __bfloat162float(qp.x);
            float qv1 = __bfloat162float(qp.y);
#pragma unroll
            for (int j = 0; j < 8; ++j) {
                acc0[j] = fmaf(qv0, Ms[e][d0 + j], acc0[j]);
                acc1[j] = fmaf(qv1, Ms[e][d0 + j], acc1[j]);
            }
        }
        __nv_bfloat16* op0 = g_osT + (size_t)tb * CN + (size_t)n * CC + h * 32 + d0;
        __nv_bfloat16* op1 = op0 + CC;
#pragma unroll
        for (int j = 0; j < 8; j += 2) {
            __nv_bfloat162 p0, p1;
            p0.x = __float2bfloat16((acc0[j] >= 8.0f) ? 1.f : 0.f);
            p0.y = __float2bfloat16((acc0[j + 1] >= 8.0f) ? 1.f : 0.f);
            p1.x = __float2bfloat16((acc1[j] >= 8.0f) ? 1.f : 0.f);
            p1.y = __float2bfloat16((acc1[j + 1] >= 8.0f) ? 1.f : 0.f);
            *(__nv_bfloat162*)(op0 + j) = p0;
            *(__nv_bfloat162*)(op1 + j) = p1;
        }
    } else {
        // bf16 panels: qs/ks2 transposed [e*10+t], vs2 natural [s*32+dd]
        __nv_bfloat16 (*qs)[321]  = (__nv_bfloat16(*)[321])dyn2;
        __nv_bfloat16 (*ks2)[321] = qs + 8;
        __nv_bfloat16 (*vs2)[321] = ks2 + 8;
        float (*at)[112] = (float(*)[112])(vs2 + 8);

        const int wid = tid >> 5;
        const int lane = tid & 31;
        const int nbh = (bx - 1440) * 8 + wid;
        const int h = nbh % HH;
        const int nb = nbh / HH;
        const int b = nb % BB;
        const int n = nb / BB;

        const __nv_bfloat16* qg = g_tq + (size_t)nbh * 320;
        const __nv_bfloat16* kg = g_tk + (size_t)nbh * 320;
        const __nv_bfloat16* vg = g_tv + (size_t)nbh * 320;

#pragma unroll
        for (int i = 0; i < TT; ++i) {
            qs[wid][lane * TT + i] = qg[i * 32 + lane];
            ks2[wid][lane * TT + i] = kg[i * 32 + lane];
            vs2[wid][i * 32 + lane] = vg[i * 32 + lane];
        }
        __syncwarp();

        for (int ii = lane; ii < 100; ii += 32) {
            int t = ii / 10, s = ii - t * 10;
            float acc = 0.f;
#pragma unroll
            for (int ee = 0; ee < 32; ++ee)
                acc = fmaf(__bfloat162float(qs[wid][ee * TT + t]),
                           __bfloat162float(ks2[wid][ee * TT + s]), acc);
            at[wid][ii] = acc;
        }
        __syncwarp();

#pragma unroll
        for (int t = 0; t < TT; ++t) {
            float acc = 0.f;
#pragma unroll
            for (int s = 0; s < TT; ++s)
                acc = fmaf(at[wid][t * 10 + s],
                           __bfloat162float(vs2[wid][s * 32 + lane]), acc);
            float sp = (acc >= 8.0f) ? 1.0f : 0.0f;
            int flat = h * 320 + t * 32 + lane;
            int tp = flat / 384;
            int cp = flat - tp * 384;
            g_osT2[(size_t)(tp * BB + b) * CN + (size_t)n * CC + cp] = __float2bfloat16(sp);
        }
    }
}

// ---------------------------------------------------------------------------
// Fused reduce_b + outer: 576 blocks, each thread handles 4 (b,c,n) columns.
// ---------------------------------------------------------------------------
__global__ void __launch_bounds__(256) k_outer(float* __restrict__ out) {
    const int i4 = (blockIdx.x * 256 + threadIdx.x) * 4;
    const int b = i4 / CN;
    const int rem = i4 - b * CN;
    const int c = rem / NN;

    float s0 = 0.f, s1 = 0.f, s2 = 0.f, s3 = 0.f;
    float ar[TT];
#pragma unroll
    for (int t = 0; t < TT; ++t) {
        union { uint64_t u; __nv_bfloat162 h2[2]; } uv;
        uv.u = *(const uint64_t*)&g_a[(size_t)t * BCN + i4];
        s0 += __bfloat162float(uv.h2[0].x);
        s1 += __bfloat162float(uv.h2[0].y);
        s2 += __bfloat162float(uv.h2[1].x);
        s3 += __bfloat162float(uv.h2[1].y);
        ar[t] = g_ared[(t * BB + b) * CC + c];
    }
    const float b0 = s0 / (float)TT;
    const float b1 = s1 / (float)TT;
    const float b2 = s2 / (float)TT;
    const float b3 = s3 / (float)TT;
#pragma unroll
    for (int t = 0; t < TT; ++t) {
        const float a = ar[t] * (1.0f / 384.0f);
        float4 w;
        w.x = a * b0; w.y = a * b1; w.z = a * b2; w.w = a * b3;
        *(float4*)(out + (size_t)t * BCN + i4) = w;
    }
}

// ---------------------------------------------------------------------------
extern "C" void kernel_launch(void* const* d_in, const int* in_sizes, int n_in,
                              void* d_out, int out_size)
{
    const float* x   = (const float*)d_in[0];
    const float* y   = (const float*)d_in[1];
    const float* sW  = (const float*)d_in[2];
    const float* sg  = (const float*)d_in[3];
    const float* sb  = (const float*)d_in[4];
    const float* tW  = (const float*)d_in[5];
    const float* tg  = (const float*)d_in[6];
    const float* tbn = (const float*)d_in[7];
    float* out = (float*)d_out;

    cudaFuncSetAttribute(k_qkv_all, cudaFuncAttributeMaxDynamicSharedMemorySize, SMEM_QKV);
    cudaFuncSetAttribute(k_final_all, cudaFuncAttributeMaxDynamicSharedMemorySize, SMEM_FIN);
    cudaFuncSetAttribute(k_phase2, cudaFuncAttributeMaxDynamicSharedMemorySize, SMEM_P2);

    // splits (+ init folded into split_w tail)
    k_split_w<<<4668, 256>>>(sW, tW);
    k_split_xy<<<11520, 256>>>(x, y);

    // all 6 qkv projections (both paths), work-queue persistent
    k_qkv_all<<<296, 256, SMEM_QKV>>>(sg, sb, tg, tbn);

    // phase 1: spatial k^T v  +  temporal gather (thin blocks)
    k_phase1<<<480 + 3 * 5760, 256>>>();

    // phase 2: spatial qM (vectorized) + temporal attention (bf16 smem union)
    k_phase2<<<1440 + (NN * BB * HH) / 8, 256, SMEM_P2>>>();

    // merged final convs (spatial fused row-mean + temporal), work-queue
    k_final_all<<<296, 256, SMEM_FIN>>>(sg, sb, tg, tbn);

    // fused reduce_b + outer product
    k_outer<<<BCN / 1024, 256>>>(out);
}

// round 17
// speedup vs baseline: 1.0131x; 1.0131x over previous
#include <cuda_runtime.h>
#include <cuda_bf16.h>
#include <cstdint>

// ---------------------------------------------------------------------------
// Spikformer spatial+temporal SSA — bf16 mma.sync, cp.async double-buffered,
// register-cached b0 fragment, work-queue persistent GEMMs, bf16 spike
// storage (binary -> exact). R14 structure + vectorized gather stores.
// ---------------------------------------------------------------------------

#define TT 10
#define BB 4
#define CC 384
#define NN 384
#define HH 12
#define CN (CC * NN)             // 147456
#define TBCN (TT * BB * CC * NN) // 5898240
#define BCN (BB * CC * NN)       // 589824

// scratch (spike tensors in bf16 — binary values, exact)
__device__ __align__(128) __nv_bfloat16 g_q[TBCN];   // spatial q spikes [tb][c][n]
__device__ __align__(128) __nv_bfloat16 g_k[TBCN];
__device__ __align__(128) __nv_bfloat16 g_v[TBCN];
__device__ __align__(128) __nv_bfloat16 g_pq[TBCN];  // temporal proj spikes [tb][c][n]
__device__ __align__(128) __nv_bfloat16 g_pk[TBCN];
__device__ __align__(128) __nv_bfloat16 g_pv[TBCN];
__device__ __align__(128) __nv_bfloat16 g_a[TBCN];   // temporal final spikes
__device__ __align__(128) __nv_bfloat16 g_tq[TBCN];  // gathered [(n*B+b)*H+h][t*32+e]
__device__ __align__(128) __nv_bfloat16 g_tk[TBCN];
__device__ __align__(128) __nv_bfloat16 g_tv[TBCN];
__device__ __align__(128) float g_M[480 * 1024];                // spatial k^T v
__device__ __align__(128) __nv_bfloat16 g_osT[TBCN];            // spatial attn spikes [tb][n][c]
__device__ __align__(128) __nv_bfloat16 g_osT2[TBCN];           // temporal attn spikes [tb][n][c]
__device__ __align__(128) __nv_bfloat16 g_Wc[8 * 3 * CN];       // [mat][comp][o][c]
__device__ __align__(128) __nv_bfloat16 g_XT[2 * 3 * 40 * CN];  // [sel][comp][tb][n][c]
__device__ float g_ared[TT * BB * CC]; // raw row sums (spatial)
__device__ unsigned g_ctr_qkv;
__device__ unsigned g_ctr_fin;

__device__ __forceinline__ uint32_t smem_u32(const void* p) {
    uint32_t a;
    asm("{ .reg .u64 t; cvta.to.shared.u64 t, %1; cvt.u32.u64 %0, t; }"
        : "=r"(a) : "l"(p));
    return a;
}

__device__ __forceinline__ void ldsm_x4(uint32_t addr, uint32_t& r0, uint32_t& r1,
                                        uint32_t& r2, uint32_t& r3) {
    asm volatile("ldmatrix.sync.aligned.m8n8.x4.shared.b16 {%0,%1,%2,%3}, [%4];"
                 : "=r"(r0), "=r"(r1), "=r"(r2), "=r"(r3) : "r"(addr));
}

__device__ __forceinline__ void mma_bf16(float* c, const uint32_t* a,
                                         uint32_t b0, uint32_t b1) {
    asm volatile(
        "mma.sync.aligned.m16n8k16.row.col.f32.bf16.bf16.f32 "
        "{%0,%1,%2,%3}, {%4,%5,%6,%7}, {%8,%9}, {%0,%1,%2,%3};"
        : "+f"(c[0]), "+f"(c[1]), "+f"(c[2]), "+f"(c[3])
        : "r"(a[0]), "r"(a[1]), "r"(a[2]), "r"(a[3]), "r"(b0), "r"(b1));
}

__device__ __forceinline__ uint32_t swz64(uint32_t off) {
    return off ^ ((off >> 3) & 0x30);
}

__device__ __forceinline__ void cp16(uint32_t dst, const void* src) {
    asm volatile("cp.async.cg.shared.global [%0], [%1], 16;" :: "r"(dst), "l"(src));
}

#define SMEM_QKV 99328
#define SMEM_FIN 66560

// ---------------------------------------------------------------------------
// fp32 -> 3x bf16 exact split precompute + init (counters, ared)
// ---------------------------------------------------------------------------
__device__ __forceinline__ void split3(float x, __nv_bfloat16& a, __nv_bfloat16& b,
                                       __nv_bfloat16& c) {
    a = __float2bfloat16(x);
    float r = x - __bfloat162float(a);
    b = __float2bfloat16(r);
    float r2 = r - __bfloat162float(b);
    c = __float2bfloat16(r2);
}

__global__ void __launch_bounds__(256) k_init() {
    int i = blockIdx.x * 256 + threadIdx.x;
    if (i < TT * BB * CC) g_ared[i] = 0.0f;
    if (i == 0) { g_ctr_qkv = 0u; g_ctr_fin = 0u; }
}

__global__ void __launch_bounds__(256) k_split_w(const float* __restrict__ sW,
                                                 const float* __restrict__ tW) {
    int i = blockIdx.x * 256 + threadIdx.x;
    float w = (i < 4 * CN) ? sW[i] : tW[i - 4 * CN];
    int m = i / CN, e = i - m * CN;
    __nv_bfloat16 c1, c2, c3;
    split3(w, c1, c2, c3);
    size_t base = (size_t)m * 3 * CN + e;
    g_Wc[base] = c1;
    g_Wc[base + CN] = c2;
    g_Wc[base + 2 * CN] = c3;
}

__global__ void __launch_bounds__(256) k_split_xy(const float* __restrict__ x,
                                                  const float* __restrict__ y) {
    __shared__ float t[32][33];
    int bx = blockIdx.x;
    int sel = bx / 5760;
    int r = bx - sel * 5760;
    int tb = r / 144, tl = r - tb * 144;
    int ct = tl / 12, nt = tl - ct * 12;
    const float* src = (sel ? y : x) + (size_t)tb * CN + (size_t)(ct * 32) * NN + nt * 32;
    int tid = threadIdx.x;
#pragma unroll
    for (int i = 0; i < 4; ++i) {
        int idx = tid + i * 256;
        int cl = idx >> 5, nl = idx & 31;
        t[cl][nl] = src[(size_t)cl * NN + nl];
    }
    __syncthreads();
#pragma unroll
    for (int i = 0; i < 4; ++i) {
        int idx = tid + i * 256;
        int nl = idx >> 5, cl = idx & 31;
        __nv_bfloat16 c1, c2, c3;
        split3(t[cl][nl], c1, c2, c3);
        size_t base = ((size_t)(sel * 3) * 40 + tb) * CN + (size_t)(nt * 32 + nl) * CC + ct * 32 + cl;
        g_XT[base] = c1;
        g_XT[base + (size_t)40 * CN] = c2;
        g_XT[base + (size_t)80 * CN] = c3;
    }
}

// ---------------------------------------------------------------------------
// cp.async double-buffered tensor-core GEMM tile, register-cached b0 fragment,
// single __syncthreads per stage. Outputs bf16 spikes (or fused row-sum).
// ---------------------------------------------------------------------------
template <int NBC>
__device__ __forceinline__ void tc_gemm_body(
    const __nv_bfloat16* __restrict__ A0,
    const __nv_bfloat16* __restrict__ B0, size_t bcs,
    const float* __restrict__ gs, const float* __restrict__ bs,
    float* __restrict__ obf, __nv_bfloat16* __restrict__ obh,
    int o0, int n0, bool suma)
{
    constexpr int NC = 3 + NBC;
    constexpr uint32_t STAGE = NC * 8192u;
    extern __shared__ char smem_raw[];
    const uint32_t ab = (smem_u32(smem_raw) + 1023u) & ~1023u;
    const int tid = threadIdx.x;
    const int lane = tid & 31;
    const int wid = tid >> 5;
    const int wm = (wid >> 2) * 64;
    const int wn = (wid & 3) * 32;

    float acc[4][4][4];
#pragma unroll
    for (int mi = 0; mi < 4; ++mi)
#pragma unroll
        for (int ni = 0; ni < 4; ++ni)
#pragma unroll
            for (int r = 0; r < 4; ++r) acc[mi][ni][r] = 0.0f;

    const int a_row_l = lane & 15;
    const int a_ch = (lane >> 4) << 4;
    const int b_row_l = ((lane >> 4) & 1) * 8 + (lane & 7);
    const int b_ch = ((lane >> 3) & 1) << 4;

    auto load_stage = [&](int s, uint32_t buf) {
#pragma unroll
        for (int i = 0; i < NC * 2; ++i) {
            int idx = tid + i * 256;
            int comp = idx >> 9;
            int rem = idx & 511;
            int row = rem >> 2, ch = rem & 3;
            const __nv_bfloat16* g =
                (comp < 3) ? (A0 + (size_t)comp * CN) : (B0 + (size_t)(comp - 3) * bcs);
            g += (size_t)row * CC + s * 32 + ch * 8;
            uint32_t d = buf + comp * 8192 + swz64((uint32_t)(row * 64 + ch * 16));
            cp16(d, g);
        }
        asm volatile("cp.async.commit_group;" ::: "memory");
    };

    auto load_bf = [&](uint32_t base, int ks, uint32_t bf[4][2]) {
#pragma unroll
        for (int bi = 0; bi < 2; ++bi) {
            int row = wn + bi * 16 + b_row_l;
            uint32_t off = (uint32_t)(row * 64 + ks * 32 + b_ch);
            uint32_t r0, r1, r2, r3;
            ldsm_x4(base + swz64(off), r0, r1, r2, r3);
            bf[bi * 2][0] = r0; bf[bi * 2][1] = r1;
            bf[bi * 2 + 1][0] = r2; bf[bi * 2 + 1][1] = r3;
        }
    };
    auto load_af = [&](uint32_t base, int ks, int mi, uint32_t* af) {
        int row = wm + mi * 16 + a_row_l;
        uint32_t off = (uint32_t)(row * 64 + ks * 32 + a_ch);
        ldsm_x4(base + swz64(off), af[0], af[1], af[2], af[3]);
    };

    load_stage(0, ab);
    for (int s = 0; s < 12; ++s) {
        const uint32_t cur = ab + (uint32_t)(s & 1) * STAGE;
        asm volatile("cp.async.wait_group 0;" ::: "memory");
        __syncthreads();
        if (s < 11) load_stage(s + 1, ab + (uint32_t)((s + 1) & 1) * STAGE);

#pragma unroll
        for (int ks = 0; ks < 2; ++ks) {
            uint32_t b0[4][2];
            load_bf(cur + 3 * 8192, ks, b0); // pb=0, cached (used by all pa)
#pragma unroll
            for (int pa = 0; pa < 3; ++pa) {
                uint32_t afr[4][4];
#pragma unroll
                for (int mi = 0; mi < 4; ++mi) load_af(cur + pa * 8192, ks, mi, afr[mi]);
#pragma unroll
                for (int mi = 0; mi < 4; ++mi)
#pragma unroll
                    for (int ni = 0; ni < 4; ++ni)
                        mma_bf16(acc[mi][ni], afr[mi], b0[ni][0], b0[ni][1]);
                if (NBC == 3) {
                    if (pa < 2) { // pb=1 (pairs (0,1),(1,1))
                        uint32_t bt[4][2];
                        load_bf(cur + 4 * 8192, ks, bt);
#pragma unroll
                        for (int mi = 0; mi < 4; ++mi)
#pragma unroll
                            for (int ni = 0; ni < 4; ++ni)
                                mma_bf16(acc[mi][ni], afr[mi], bt[ni][0], bt[ni][1]);
                    }
                    if (pa == 0) { // pb=2 (pair (0,2))
                        uint32_t bt[4][2];
                        load_bf(cur + 5 * 8192, ks, bt);
#pragma unroll
                        for (int mi = 0; mi < 4; ++mi)
#pragma unroll
                            for (int ni = 0; ni < 4; ++ni)
                                mma_bf16(acc[mi][ni], afr[mi], bt[ni][0], bt[ni][1]);
                    }
                }
            }
        }
    }

    // epilogue: BN + spike. row = channel index (always in [0,384)).
#pragma unroll
    for (int mi = 0; mi < 4; ++mi) {
#pragma unroll
        for (int half = 0; half < 2; ++half) {
            const int row = o0 + wm + mi * 16 + half * 8 + (lane >> 2);
            const float gv = gs[row];
            const float bv = bs[row];
            float vals[8];
#pragma unroll
            for (int ni = 0; ni < 4; ++ni) {
                vals[ni * 2 + 0] = (fmaf(acc[mi][ni][half * 2 + 0], gv, bv) >= 2.0f) ? 1.f : 0.f;
                vals[ni * 2 + 1] = (fmaf(acc[mi][ni][half * 2 + 1], gv, bv) >= 2.0f) ? 1.f : 0.f;
            }
            if (suma) {
                float sum = 0.f;
#pragma unroll
                for (int j = 0; j < 8; ++j) sum += vals[j];
                sum += __shfl_xor_sync(0xffffffffu, sum, 1);
                sum += __shfl_xor_sync(0xffffffffu, sum, 2);
                if ((lane & 3) == 0) atomicAdd(&obf[row], sum);
            } else {
                __nv_bfloat16* dst = obh + (size_t)row * NN + n0 + wn + (lane & 3) * 2;
#pragma unroll
                for (int ni = 0; ni < 4; ++ni) {
                    __nv_bfloat162 w;
                    w.x = __float2bfloat16(vals[ni * 2 + 0]);
                    w.y = __float2bfloat16(vals[ni * 2 + 1]);
                    *(__nv_bfloat162*)(dst + ni * 8) = w;
                }
            }
        }
    }
}

// Work-queue persistent qkv for BOTH paths: 2160 tiles.
__global__ void __launch_bounds__(256, 2) k_qkv_all(
    const float* __restrict__ sg, const float* __restrict__ sb,
    const float* __restrict__ tg, const float* __restrict__ tb_)
{
    __shared__ unsigned s_tile;
    for (;;) {
        if (threadIdx.x == 0) s_tile = atomicAdd(&g_ctr_qkv, 1u);
        __syncthreads();
        unsigned tile = s_tile;
        if (tile >= 2160u) break;
        int nx = tile % 3;
        int rest = tile / 3;
        int my = rest % 3;
        int z = rest / 3;
        int pj = z / 40, tb = z - pj * 40;
        int path = pj / 3, j = pj - path * 3;
        int o0 = my * 128, n0 = nx * 128;
        const __nv_bfloat16* A0 = g_Wc + (size_t)((path * 4 + j) * 3) * CN + (size_t)o0 * CC;
        int sel = (j == 0) ? 0 : 1;
        const __nv_bfloat16* B0 = g_XT + ((size_t)(sel * 3) * 40 + tb) * CN + (size_t)n0 * CC;
        __nv_bfloat16* Ob;
        if (path == 0) Ob = (j == 0) ? g_q : (j == 1) ? g_k : g_v;
        else           Ob = (j == 0) ? g_pq : (j == 1) ? g_pk : g_pv;
        const float* gs = (path == 0) ? sg : tg;
        const float* bs = (path == 0) ? sb : tb_;
        tc_gemm_body<3>(A0, B0, (size_t)40 * CN, gs + j * CC, bs + j * CC,
                        nullptr, Ob + (size_t)tb * CN, o0, n0, false);
        __syncthreads();
    }
}

// Work-queue persistent merged final convs: 720 tiles.
__global__ void __launch_bounds__(256, 2) k_final_all(
    const float* __restrict__ sg, const float* __restrict__ sb,
    const float* __restrict__ tg, const float* __restrict__ tb_)
{
    __shared__ unsigned s_tile;
    for (;;) {
        if (threadIdx.x == 0) s_tile = atomicAdd(&g_ctr_fin, 1u);
        __syncthreads();
        unsigned tile = s_tile;
        if (tile >= 720u) break;
        int nx = tile % 3;
        int rest = tile / 3;
        int my = rest % 3;
        int z = rest / 3;
        int path = z / 40, tb = z - path * 40;
        int o0 = my * 128, n0 = nx * 128;
        const __nv_bfloat16* A0 = g_Wc + (size_t)((path * 4 + 3) * 3) * CN + (size_t)o0 * CC;
        const __nv_bfloat16* B0 =
            ((path == 0) ? g_osT : g_osT2) + (size_t)tb * CN + (size_t)n0 * CC;
        const float* gs = (path == 0) ? sg : tg;
        const float* bs = (path == 0) ? sb : tb_;
        tc_gemm_body<1>(A0, B0, 0, gs + 3 * CC, bs + 3 * CC,
                        g_ared + (size_t)tb * CC, g_a + (size_t)tb * CN,
                        o0, n0, path == 0);
        __syncthreads();
    }
}

// ---------------------------------------------------------------------------
// Phase 1 (merged): spatial kvM (blocks 0..479) + temporal gather (480..17759)
// Gather stores vectorized: one 8B store per thread (4 consecutive ee).
// ---------------------------------------------------------------------------
__global__ void __launch_bounds__(256) k_phase1() {
    const int bx = blockIdx.x;
    const int tid = threadIdx.x;
    if (bx < 480) {
        __shared__ float ks[64][33];
        __shared__ float vs[64][33];
        const int tb = bx / HH;
        const int h = bx - tb * HH;
        const size_t base = (size_t)tb * CN + (size_t)h * 32 * NN;
        const __nv_bfloat16* kb = g_k + base;
        const __nv_bfloat16* vb = g_v + base;

        const int e = tid >> 3;
        const int dd0 = (tid & 7) << 2;
        float mc0 = 0.f, mc1 = 0.f, mc2 = 0.f, mc3 = 0.f;
        for (int m0 = 0; m0 < NN; m0 += 64) {
#pragma unroll
            for (int i = 0; i < 8; ++i) {
                int idx = tid + i * 256;
                int ee = idx >> 6, mm = idx & 63;
                ks[mm][ee] = __bfloat162float(kb[(size_t)ee * NN + m0 + mm]);
                vs[mm][ee] = __bfloat162float(vb[(size_t)ee * NN + m0 + mm]);
            }
            __syncthreads();
#pragma unroll 8
            for (int mm = 0; mm < 64; ++mm) {
                float kv = ks[mm][e];
                mc0 = fmaf(kv, vs[mm][dd0 + 0], mc0);
                mc1 = fmaf(kv, vs[mm][dd0 + 1], mc1);
                mc2 = fmaf(kv, vs[mm][dd0 + 2], mc2);
                mc3 = fmaf(kv, vs[mm][dd0 + 3], mc3);
            }
            __syncthreads();
        }
        float* Mp = g_M + (size_t)bx * 1024 + e * 32 + dd0;
        Mp[0] = mc0; Mp[1] = mc1; Mp[2] = mc2; Mp[3] = mc3;
    } else {
        // temporal gather: dst[((n*B+b)*H+h)*320 + t*32 + e]
        __shared__ __nv_bfloat16 tile[32][33];
        const int r0 = bx - 480;
        const int which = r0 / 5760;
        const int r = r0 - which * 5760;
        const int ntile = r % 12;
        const int tbh = r / 12;
        const int tb = tbh / 12;
        const int h = tbh - tb * 12;
        const int t = tb / BB;
        const int b = tb - t * BB;

        const __nv_bfloat16* srcbase = (which == 0) ? g_pq : (which == 1) ? g_pk : g_pv;
        __nv_bfloat16* dst = (which == 0) ? g_tq : (which == 1) ? g_tk : g_tv;
        const __nv_bfloat16* src = srcbase + (size_t)tb * CN + (size_t)h * 32 * NN + ntile * 32;

#pragma unroll
        for (int i = 0; i < 4; ++i) {
            int idx = tid + i * 256;
            int ee = idx >> 5, nn = idx & 31;
            tile[ee][nn] = src[(size_t)ee * NN + nn];
        }
        __syncthreads();
        // one 8B store per thread: nn = tid>>3, eg = (tid&7)*4 (ee group)
        {
            const int nn = tid >> 3;
            const int eg = (tid & 7) << 2;
            const int n = ntile * 32 + nn;
            union { uint64_t u; __nv_bfloat16 h4[4]; } pk;
            pk.h4[0] = tile[eg + 0][nn];
            pk.h4[1] = tile[eg + 1][nn];
            pk.h4[2] = tile[eg + 2][nn];
            pk.h4[3] = tile[eg + 3][nn];
            *(uint64_t*)&dst[((size_t)(n * BB + b) * HH + h) * 320 + t * 32 + eg] = pk.u;
        }
    }
}

// ---------------------------------------------------------------------------
// Phase 2 (merged): spatial qM (blocks 0..1439, 2 n/thread via bf162 loads)
// + temporal attn (1440..3743)
// ---------------------------------------------------------------------------
__global__ void __launch_bounds__(256) k_phase2() {
    const int bx = blockIdx.x;
    const int tid = threadIdx.x;
    if (bx < 1440) {
        __shared__ float Ms[32][32];
        const int tbh = bx / 3;
        const int nt = bx - tbh * 3;
        const int tb = tbh / HH;
        const int h = tbh - tb * HH;

#pragma unroll
        for (int i = 0; i < 4; ++i) {
            int idx = tid + i * 256;
            Ms[idx >> 5][idx & 31] = g_M[(size_t)tbh * 1024 + idx];
        }
        __syncthreads();

        const int np = tid & 63;
        const int n = nt * 128 + np * 2;
        const int d0 = (tid >> 6) * 8;
        const __nv_bfloat16* qb = g_q + (size_t)tb * CN + (size_t)h * 32 * NN + n;

        float acc0[8], acc1[8];
#pragma unroll
        for (int j = 0; j < 8; ++j) { acc0[j] = 0.f; acc1[j] = 0.f; }
#pragma unroll
        for (int e = 0; e < 32; ++e) {
            __nv_bfloat162 qp = *(const __nv_bfloat162*)(qb + (size_t)e * NN);
            float qv0 = __bfloat162float(qp.x);
            float qv1 = __bfloat162float(qp.y);
#pragma unroll
            for (int j = 0; j < 8; ++j) {
                acc0[j] = fmaf(qv0, Ms[e][d0 + j], acc0[j]);
                acc1[j] = fmaf(qv1, Ms[e][d0 + j], acc1[j]);
            }
        }
        __nv_bfloat16* op0 = g_osT + (size_t)tb * CN + (size_t)n * CC + h * 32 + d0;
        __nv_bfloat16* op1 = op0 + CC;
#pragma unroll
        for (int j = 0; j < 8; j += 2) {
            __nv_bfloat162 p0, p1;
            p0.x = __float2bfloat16((acc0[j] >= 8.0f) ? 1.f : 0.f);
            p0.y = __float2bfloat16((acc0[j + 1] >= 8.0f) ? 1.f : 0.f);
            p1.x = __float2bfloat16((acc1[j] >= 8.0f) ? 1.f : 0.f);
            p1.y = __float2bfloat16((acc1[j + 1] >= 8.0f) ? 1.f : 0.f);
            *(__nv_bfloat162*)(op0 + j) = p0;
            *(__nv_bfloat162*)(op1 + j) = p1;
        }
    } else {
        __shared__ float qs[8][321];
        __shared__ float ks2[8][321];
        __shared__ float vs2[8][321];
        __shared__ float at[8][112];

        const int wid = tid >> 5;
        const int lane = tid & 31;
        const int nbh = (bx - 1440) * 8 + wid;
        const int h = nbh % HH;
        const int nb = nbh / HH;
        const int b = nb % BB;
        const int n = nb / BB;

        const __nv_bfloat16* qg = g_tq + (size_t)nbh * 320;
        const __nv_bfloat16* kg = g_tk + (size_t)nbh * 320;
        const __nv_bfloat16* vg = g_tv + (size_t)nbh * 320;

#pragma unroll
        for (int i = 0; i < TT; ++i) {
            qs[wid][lane * TT + i] = __bfloat162float(qg[i * 32 + lane]);
            ks2[wid][lane * TT + i] = __bfloat162float(kg[i * 32 + lane]);
            vs2[wid][i * 32 + lane] = __bfloat162float(vg[i * 32 + lane]);
        }
        __syncwarp();

        for (int ii = lane; ii < 100; ii += 32) {
            int t = ii / 10, s = ii - t * 10;
            float acc = 0.f;
#pragma unroll
            for (int ee = 0; ee < 32; ++ee)
                acc = fmaf(qs[wid][ee * TT + t], ks2[wid][ee * TT + s], acc);
            at[wid][ii] = acc;
        }
        __syncwarp();

#pragma unroll
        for (int t = 0; t < TT; ++t) {
            float acc = 0.f;
#pragma unroll
            for (int s = 0; s < TT; ++s)
                acc = fmaf(at[wid][t * 10 + s], vs2[wid][s * 32 + lane], acc);
            float sp = (acc >= 8.0f) ? 1.0f : 0.0f;
            int flat = h * 320 + t * 32 + lane;
            int tp = flat / 384;
            int cp = flat - tp * 384;
            g_osT2[(size_t)(tp * BB + b) * CN + (size_t)n * CC + cp] = __float2bfloat16(sp);
        }
    }
}

// ---------------------------------------------------------------------------
// Fused reduce_b + outer: 576 blocks, each thread handles 4 (b,c,n) columns.
// ---------------------------------------------------------------------------
__global__ void __launch_bounds__(256) k_outer(float* __restrict__ out) {
    const int i4 = (blockIdx.x * 256 + threadIdx.x) * 4;
    const int b = i4 / CN;
    const int rem = i4 - b * CN;
    const int c = rem / NN;

    float s0 = 0.f, s1 = 0.f, s2 = 0.f, s3 = 0.f;
    float ar[TT];
#pragma unroll
    for (int t = 0; t < TT; ++t) {
        union { uint64_t u; __nv_bfloat162 h2[2]; } uv;
        uv.u = *(const uint64_t*)&g_a[(size_t)t * BCN + i4];
        s0 += __bfloat162float(uv.h2[0].x);
        s1 += __bfloat162float(uv.h2[0].y);
        s2 += __bfloat162float(uv.h2[1].x);
        s3 += __bfloat162float(uv.h2[1].y);
        ar[t] = g_ared[(t * BB + b) * CC + c];
    }
    const float b0 = s0 / (float)TT;
    const float b1 = s1 / (float)TT;
    const float b2 = s2 / (float)TT;
    const float b3 = s3 / (float)TT;
#pragma unroll
    for (int t = 0; t < TT; ++t) {
        const float a = ar[t] * (1.0f / 384.0f);
        float4 w;
        w.x = a * b0; w.y = a * b1; w.z = a * b2; w.w = a * b3;
        *(float4*)(out + (size_t)t * BCN + i4) = w;
    }
}

// ---------------------------------------------------------------------------
extern "C" void kernel_launch(void* const* d_in, const int* in_sizes, int n_in,
                              void* d_out, int out_size)
{
    const float* x   = (const float*)d_in[0];
    const float* y   = (const float*)d_in[1];
    const float* sW  = (const float*)d_in[2];
    const float* sg  = (const float*)d_in[3];
    const float* sb  = (const float*)d_in[4];
    const float* tW  = (const float*)d_in[5];
    const float* tg  = (const float*)d_in[6];
    const float* tbn = (const float*)d_in[7];
    float* out = (float*)d_out;

    cudaFuncSetAttribute(k_qkv_all, cudaFuncAttributeMaxDynamicSharedMemorySize, SMEM_QKV);
    cudaFuncSetAttribute(k_final_all, cudaFuncAttributeMaxDynamicSharedMemorySize, SMEM_FIN);

    // init + precompute splits (R14 structure)
    k_init<<<60, 256>>>();
    k_split_w<<<4608, 256>>>(sW, tW);
    k_split_xy<<<11520, 256>>>(x, y);

    // all 6 qkv projections (both paths), work-queue persistent
    k_qkv_all<<<296, 256, SMEM_QKV>>>(sg, sb, tg, tbn);

    // phase 1: spatial k^T v  +  temporal gather (thin blocks, wide stores)
    k_phase1<<<480 + 3 * 5760, 256>>>();

    // phase 2: spatial qM (vectorized)  +  temporal attention
    k_phase2<<<1440 + (NN * BB * HH) / 8, 256>>>();

    // merged final convs (spatial fused row-mean + temporal), work-queue
    k_final_all<<<296, 256, SMEM_FIN>>>(sg, sb, tg, tbn);

    // fused reduce_b + outer product
    k_outer<<<BCN / 1024, 256>>>(out);
}